// round 9
// baseline (speedup 1.0000x reference)
#include <cuda_runtime.h>
#include <cstdint>

#define H 4096
#define NUM_LAYERS 8
#define NBLOCKS 256
#define NTHREADS 512              // 16 warps -> 4096 warps == one per row
#define WARPS (NTHREADS / 32)

// Prefetch: first 4 KB of each row (cols 0..1023) via TMA across the barrier.
#define PF_ROW_BYTES 4096
#define PF_F4_LANE 8              // 8 float4 per lane
#define PF_TOTAL (WARPS * PF_ROW_BYTES)     // 64 KB

// Dynamic smem layout (byte offsets)
#define SMEM_X 0                            // 16 KB x vector
#define SMEM_PF 16384                       // 64 KB weight prefetch
#define SMEM_MBAR (SMEM_PF + PF_TOTAL)
#define SMEM_TOTAL (SMEM_MBAR + 16)

// Ping-pong hidden-state buffers (allocation-free scratch).
__device__ float g_h[2][H];

// Software grid-barrier state (monotonic across graph replays).
__device__ unsigned g_bar_count = 0;
__device__ unsigned g_bar_phase = 0;

__device__ __forceinline__ void grid_barrier() {
    __syncthreads();
    if (threadIdx.x == 0) {
        const unsigned target = *(volatile unsigned*)&g_bar_phase + 1;
        __threadfence();
        const unsigned old = atomicAdd(&g_bar_count, 1);
        if (old == NBLOCKS - 1) {
            *(volatile unsigned*)&g_bar_count = 0;
            __threadfence();
            atomicAdd(&g_bar_phase, 1);
        } else {
            while (*(volatile unsigned*)&g_bar_phase < target)
                __nanosleep(64);
        }
        __threadfence();
    }
    __syncthreads();
}

__device__ __forceinline__ uint32_t smem_u32(const void* p) {
    uint32_t a;
    asm("{ .reg .u64 t; cvta.to.shared.u64 t, %1; cvt.u32.u64 %0, t; }"
        : "=r"(a) : "l"(p));
    return a;
}
__device__ __forceinline__ void mbar_init(uint32_t mbar, uint32_t count) {
    asm volatile("mbarrier.init.shared.b64 [%0], %1;" :: "r"(mbar), "r"(count) : "memory");
}
__device__ __forceinline__ void mbar_expect_tx(uint32_t mbar, uint32_t bytes) {
    asm volatile("mbarrier.arrive.expect_tx.shared.b64 _, [%0], %1;"
                 :: "r"(mbar), "r"(bytes) : "memory");
}
__device__ __forceinline__ void mbar_wait(uint32_t mbar, uint32_t parity) {
    asm volatile(
        "{\n\t.reg .pred P;\n\t"
        "W_%=:\n\t"
        "mbarrier.try_wait.parity.acquire.cta.shared::cta.b64 P, [%0], %1, 0x989680;\n\t"
        "@P bra D_%=;\n\t"
        "bra W_%=;\n\t"
        "D_%=:\n\t}"
        :: "r"(mbar), "r"(parity) : "memory");
}
__device__ __forceinline__ void bulk_cp(uint32_t dst_smem, const void* src_gmem,
                                        uint32_t bytes, uint32_t mbar) {
    asm volatile(
        "cp.async.bulk.shared::cluster.global.mbarrier::complete_tx::bytes "
        "[%0], [%1], %2, [%3];"
        :: "r"(dst_smem), "l"(src_gmem), "r"(bytes), "r"(mbar) : "memory");
}

// Persistent fused RNN with cross-barrier weight prefetch.
// Per layer: the first 1024 cols of each warp's row come from a TMA prefetch
// issued during the PREVIOUS layer (weights are h-independent), so DRAM stays
// busy through the grid-barrier seam; the remaining 3072 cols stream via LDG.
__global__ void __launch_bounds__(NTHREADS, 2)
rnn_fused_kernel(const float* __restrict__ x,
                 const float* __restrict__ Wxh,
                 const float* __restrict__ bxh,
                 const float* __restrict__ bhh,
                 const float* __restrict__ fc_w,
                 const float* __restrict__ fc_b,
                 float* __restrict__ out) {
    extern __shared__ char smem[];
    const uint32_t sbase = smem_u32(smem);
    const uint32_t mbar = sbase + SMEM_MBAR;
    float4* sh4 = reinterpret_cast<float4*>(smem + SMEM_X);

    const int warp = threadIdx.x >> 5;
    const int lane = threadIdx.x & 31;
    const int row  = blockIdx.x * WARPS + warp;   // 0..4095
    const int row0 = blockIdx.x * WARPS;

    // Prologue: arm mbar and prefetch layer 0's row heads while x stages.
    if (threadIdx.x == 0) {
        mbar_init(mbar, 1);
        asm volatile("fence.proxy.async.shared::cta;" ::: "memory");
        mbar_expect_tx(mbar, PF_TOTAL);
        #pragma unroll
        for (int r = 0; r < WARPS; r++)
            bulk_cp(sbase + SMEM_PF + r * PF_ROW_BYTES,
                    Wxh + (size_t)(row0 + r) * H, PF_ROW_BYTES, mbar);
    }

    const float* cur = x;
    int pf_phase = 0;

    #pragma unroll 1
    for (int l = 0; l <= NUM_LAYERS; l++) {           // 8 tanh layers + fc
        const bool last = (l == NUM_LAYERS);
        const float* Wl = last ? fc_w : Wxh + (size_t)l * H * H;

        // Stage this layer's input vector into smem.
        const float4* xg = reinterpret_cast<const float4*>(cur);
        #pragma unroll
        for (int i = threadIdx.x; i < H / 4; i += NTHREADS)
            sh4[i] = xg[i];
        __syncthreads();

        float acc[4] = {0.f, 0.f, 0.f, 0.f};

        // 1) Consume the prefetched head of the row (cols 0..1023) from smem.
        mbar_wait(mbar, pf_phase);
        pf_phase ^= 1;
        {
            const float4* pfr = reinterpret_cast<const float4*>(
                smem + SMEM_PF + warp * PF_ROW_BYTES);
            #pragma unroll
            for (int j = 0; j < PF_F4_LANE; j++) {
                float4 w4 = pfr[lane + j * 32];
                float4 xv = sh4[lane + j * 32];
                acc[j & 3] += w4.x * xv.x + w4.y * xv.y
                            + w4.z * xv.z + w4.w * xv.w;
            }
        }
        __syncthreads();   // everyone done with the prefetch buffer

        // 2) Re-arm the prefetch with the NEXT layer's row heads (h-independent),
        //    so TMA streams while we LDG the tail and spin at the barrier.
        if (threadIdx.x == 0 && !last) {
            const float* Wn = (l + 1 == NUM_LAYERS) ? fc_w
                                                    : Wxh + (size_t)(l + 1) * H * H;
            mbar_expect_tx(mbar, PF_TOTAL);
            #pragma unroll
            for (int r = 0; r < WARPS; r++)
                bulk_cp(sbase + SMEM_PF + r * PF_ROW_BYTES,
                        Wn + (size_t)(row0 + r) * H, PF_ROW_BYTES, mbar);
        }

        // 3) LDG the remaining 3072 cols (24 float4/lane) in batches of 4.
        {
            const float4* Wr = reinterpret_cast<const float4*>(
                Wl + (size_t)row * H) + (PF_ROW_BYTES / 16);
            const float4* xt = sh4 + (PF_ROW_BYTES / 16);
            #pragma unroll
            for (int i = 0; i < 24; i += 4) {
                float4 w[4];
                #pragma unroll
                for (int j = 0; j < 4; j++)
                    w[j] = Wr[lane + (i + j) * 32];
                #pragma unroll
                for (int j = 0; j < 4; j++) {
                    float4 xv = xt[lane + (i + j) * 32];
                    acc[j] += w[j].x * xv.x + w[j].y * xv.y
                            + w[j].z * xv.z + w[j].w * xv.w;
                }
            }
        }

        float a = (acc[0] + acc[1]) + (acc[2] + acc[3]);
        #pragma unroll
        for (int off = 16; off; off >>= 1)
            a += __shfl_down_sync(0xffffffffu, a, off);

        if (last) {
            if (lane == 0)
                out[row] = a + fc_b[row];
        } else {
            if (lane == 0)
                g_h[l & 1][row] = tanhf(a + bxh[l * H + row] + bhh[l * H + row]);
            grid_barrier();           // publish h before anyone reads it
            cur = g_h[l & 1];
        }
    }
}

extern "C" void kernel_launch(void* const* d_in, const int* in_sizes, int n_in,
                              void* d_out, int out_size) {
    const float* x    = (const float*)d_in[0];  // [1, H]
    const float* Wxh  = (const float*)d_in[1];  // [L, H, H]
    const float* bxh  = (const float*)d_in[2];  // [L, H]
    // d_in[3] = Whh — multiplied by a zero vector in the reference; never read.
    const float* bhh  = (const float*)d_in[4];  // [L, H]
    const float* fc_w = (const float*)d_in[5];  // [H, H]
    const float* fc_b = (const float*)d_in[6];  // [H]
    float* out = (float*)d_out;

    cudaFuncSetAttribute(rnn_fused_kernel,
                         cudaFuncAttributeMaxDynamicSharedMemorySize, SMEM_TOTAL);

    rnn_fused_kernel<<<NBLOCKS, NTHREADS, SMEM_TOTAL>>>(
        x, Wxh, bxh, bhh, fc_w, fc_b, out);
}

// round 10
// speedup vs baseline: 1.1109x; 1.1109x over previous
#include <cuda_runtime.h>
#include <cstdint>

#define H 4096
#define NUM_LAYERS 8
#define NBLOCKS 148            // exactly one block per SM -> balanced LDG streams
#define NTHREADS 1024          // 32 warps/block
#define WARPS (NTHREADS / 32)

// Row partition: 4096 rows over 148 blocks = 100 blocks with 28, 48 with 27.
#define BASE_ROWS 27
#define EXTRA_BLOCKS 100

// Ping-pong hidden-state buffers (allocation-free scratch).
__device__ float g_h[2][H];

// Software grid-barrier state (monotonic across graph replays).
__device__ unsigned g_bar_count = 0;
__device__ unsigned g_bar_phase = 0;

// Grid-wide barrier. Safe: 148 blocks of 1024 threads = 1 block/SM, all
// co-resident. Release publishes prior writes via gpu-scope fences.
__device__ __forceinline__ void grid_barrier() {
    __syncthreads();
    if (threadIdx.x == 0) {
        const unsigned target = *(volatile unsigned*)&g_bar_phase + 1;
        __threadfence();
        const unsigned old = atomicAdd(&g_bar_count, 1);
        if (old == NBLOCKS - 1) {
            *(volatile unsigned*)&g_bar_count = 0;
            __threadfence();
            atomicAdd(&g_bar_phase, 1);
        } else {
            while (*(volatile unsigned*)&g_bar_phase < target)
                __nanosleep(64);
        }
        __threadfence();
    }
    __syncthreads();
}

// One warp computes dot(W[row,:], x_smem): batch-4 LDG.128 schedule
// (4 independent loads in flight; proven best per-warp shape).
__device__ __forceinline__ float row_dot(const float* __restrict__ W,
                                         const float4* __restrict__ sh4,
                                         int row, int lane) {
    const float4* Wr = reinterpret_cast<const float4*>(W + (size_t)row * H);
    float acc[4] = {0.f, 0.f, 0.f, 0.f};
    #pragma unroll
    for (int i = 0; i < 32; i += 4) {
        float4 w[4];
        #pragma unroll
        for (int j = 0; j < 4; j++)
            w[j] = Wr[lane + (i + j) * 32];
        #pragma unroll
        for (int j = 0; j < 4; j++) {
            float4 xv = sh4[lane + (i + j) * 32];
            acc[j] += w[j].x * xv.x + w[j].y * xv.y
                    + w[j].z * xv.z + w[j].w * xv.w;
        }
    }
    float a = (acc[0] + acc[1]) + (acc[2] + acc[3]);
    #pragma unroll
    for (int off = 16; off; off >>= 1)
        a += __shfl_down_sync(0xffffffffu, a, off);
    return a;
}

// Whole network in one persistent kernel (R8 structure), with the grid sized
// to exactly 1 block per SM so every SM streams the same number of weight
// rows per layer (27-28). Removes the 2:1 per-SM load imbalance that made
// 40 of 148 SMs idle at each grid barrier in the 256-block version.
__global__ void __launch_bounds__(NTHREADS, 1)
rnn_fused_kernel(const float* __restrict__ x,
                 const float* __restrict__ Wxh,
                 const float* __restrict__ bxh,
                 const float* __restrict__ bhh,
                 const float* __restrict__ fc_w,
                 const float* __restrict__ fc_b,
                 float* __restrict__ out) {
    __shared__ float4 sh4[H / 4];   // 16 KB: current input vector

    const int warp = threadIdx.x >> 5;
    const int lane = threadIdx.x & 31;
    const int b    = blockIdx.x;

    // Contiguous row chunk for this block (27 or 28 rows).
    const int extra = (b < EXTRA_BLOCKS) ? b : EXTRA_BLOCKS;
    const int start = b * BASE_ROWS + extra;
    const int cnt   = BASE_ROWS + (b < EXTRA_BLOCKS ? 1 : 0);
    const bool active = (warp < cnt);
    const int row = start + warp;

    const float* cur = x;

    #pragma unroll 1
    for (int l = 0; l < NUM_LAYERS; l++) {
        // Stage the layer input (16 KB) into shared memory.
        const float4* xg = reinterpret_cast<const float4*>(cur);
        #pragma unroll
        for (int i = threadIdx.x; i < H / 4; i += NTHREADS)
            sh4[i] = xg[i];
        __syncthreads();

        if (active) {
            const float a = row_dot(Wxh + (size_t)l * H * H, sh4, row, lane);
            if (lane == 0)
                g_h[l & 1][row] = tanhf(a + bxh[l * H + row] + bhh[l * H + row]);
        }

        grid_barrier();               // publish h before anyone reads it
        cur = g_h[l & 1];
    }

    // Final linear layer (no tanh, single bias) -> d_out.
    {
        const float4* xg = reinterpret_cast<const float4*>(cur);
        #pragma unroll
        for (int i = threadIdx.x; i < H / 4; i += NTHREADS)
            sh4[i] = xg[i];
        __syncthreads();

        if (active) {
            const float a = row_dot(fc_w, sh4, row, lane);
            if (lane == 0)
                out[row] = a + fc_b[row];
        }
    }
}

extern "C" void kernel_launch(void* const* d_in, const int* in_sizes, int n_in,
                              void* d_out, int out_size) {
    const float* x    = (const float*)d_in[0];  // [1, H]
    const float* Wxh  = (const float*)d_in[1];  // [L, H, H]
    const float* bxh  = (const float*)d_in[2];  // [L, H]
    // d_in[3] = Whh — multiplied by a zero vector in the reference; never read.
    const float* bhh  = (const float*)d_in[4];  // [L, H]
    const float* fc_w = (const float*)d_in[5];  // [H, H]
    const float* fc_b = (const float*)d_in[6];  // [H]
    float* out = (float*)d_out;

    rnn_fused_kernel<<<NBLOCKS, NTHREADS>>>(x, Wxh, bxh, bhh, fc_w, fc_b, out);
}